// round 4
// baseline (speedup 1.0000x reference)
#include <cuda_runtime.h>
#include <math.h>
#include <cstdint>

#define FULL_MASK 0xFFFFFFFFu

// Batch bs=65536, S=10, D=100, H=16, 5 greedy steps.
// One warp per batch. lane = (h = lane&15, g = lane>>4); lane computes ic[s][h] for s in {5g..5g+4}.
//
// Numerics contract (to bit-match XLA's fp32 lowering and avoid argmax flips):
//   - every dot is a single-accumulator sequential-k fmaf chain (k ascending)
//   - bias added AFTER the full reduction
//   - src = mean(ui) = IEEE fp32 divide of the sequential running sum by t
//   - softmax skipped (monotone => argmax-invariant); first-index tie-break
__global__ __launch_bounds__(128, 6)
void attn_greedy_kernel(const float* __restrict__ g_ui,     // [bs,16]
                        const float* __restrict__ g_corp,   // [bs,10,100]
                        const float* __restrict__ g_wp,     // [100,16]
                        const float* __restrict__ g_bp,     // [16]
                        const float* __restrict__ g_wk,     // [16,16]
                        const float* __restrict__ g_bk,     // [16]
                        float* __restrict__ g_out,          // [bs,6,16]
                        int n_batch)
{
    __shared__ __align__(16) float s_corp[4][1000];   // per-warp corpus tile (row stride 100)
    __shared__ float s_ic[4][10][17];                 // ic; stride 17: conflict-free score reads
    __shared__ float s_src[4][16];                    // current mean(ui) vector
    __shared__ float s_wpT[16][100];                  // W_proj transposed: s_wpT[h][d]

    const int tid  = threadIdx.x;
    const int w    = tid >> 5;
    const int lane = tid & 31;
    const int h    = lane & 15;
    const int g    = lane >> 4;

    // Stage W_proj transposed (once per block).
    for (int i = tid; i < 1600; i += 128) {
        int d = i >> 4, hh = i & 15;
        s_wpT[hh][d] = g_wp[d * 16 + hh];
    }
    // Per-lane W_k column cache (k ascending order preserved in the fma chain).
    float wk[16];
    #pragma unroll
    for (int k = 0; k < 16; k++) wk[k] = g_wk[k * 16 + h];
    const float bp_h = g_bp[h];
    const float bk_h = g_bk[h];
    __syncthreads();

    const int wg = (blockIdx.x << 2) + w;
    const int nw = gridDim.x << 2;

    for (int b = wg; b < n_batch; b += nw) {
        // ---- stage corpus tile (coalesced float4, raw fp32) ----
        const float4* src4 = (const float4*)(g_corp + (size_t)b * 1000);
        float4* dst4 = (float4*)s_corp[w];
        #pragma unroll
        for (int i = 0; i < 8; i++) {
            int idx = lane + 32 * i;
            if (idx < 250) dst4[idx] = src4[idx];
        }
        float u_h   = g_ui[(size_t)b * 16 + h];
        float sum_h = u_h;                        // running fp32 sum of ui vectors (append order)
        if (g == 0) {
            g_out[(size_t)b * 96 + h] = u_h;
            s_src[w][h] = u_h;                    // mean of 1 vector == u (exact)
        }
        __syncwarp();

        // ---- projection: ic0[s][h] = seq-fma_{d=0..99} corpus[s,d]*Wp[d,h], then + bp[h] ----
        float acc[5] = {0.f, 0.f, 0.f, 0.f, 0.f};
        const float* crow = &s_corp[w][5 * g * 100];
        #pragma unroll
        for (int c = 0; c < 25; c++) {
            float w0 = s_wpT[h][4*c], w1 = s_wpT[h][4*c+1], w2 = s_wpT[h][4*c+2], w3 = s_wpT[h][4*c+3];
            #pragma unroll
            for (int j = 0; j < 5; j++) {
                float4 cv = *(const float4*)(crow + j * 100 + 4 * c);
                acc[j] = fmaf(cv.x, w0, acc[j]);   // d ascending: 4c, 4c+1, 4c+2, 4c+3
                acc[j] = fmaf(cv.y, w1, acc[j]);
                acc[j] = fmaf(cv.z, w2, acc[j]);
                acc[j] = fmaf(cv.w, w3, acc[j]);
            }
        }
        #pragma unroll
        for (int j = 0; j < 5; j++)
            s_ic[w][5*g + j][h] = acc[j] + bp_h;   // bias after full reduction
        __syncwarp();

        // ---- 5 greedy steps ----
        #pragma unroll
        for (int t = 1; t <= 5; t++) {
            // ic_new[s][h] = seq-fma_{k=0..15} ic[s][k]*Wk[k][h], then + bk[h]
            float nic[5];
            #pragma unroll
            for (int j = 0; j < 5; j++) {
                float a = 0.f;
                #pragma unroll
                for (int k = 0; k < 16; k++)
                    a = fmaf(s_ic[w][5*g + j][k], wk[k], a);   // k ascending
                nic[j] = a + bk_h;
            }
            __syncwarp();                          // all reads of old ic done
            #pragma unroll
            for (int j = 0; j < 5; j++)
                s_ic[w][5*g + j][h] = nic[j];
            __syncwarp();                          // new ic visible

            // score[s] = seq-fma_{h=0..15} ic_new[s,h]*src[h]  (lane s<10 owns s)
            float sc = -INFINITY;
            if (lane < 10) {
                sc = 0.f;
                #pragma unroll
                for (int k = 0; k < 16; k++)
                    sc = fmaf(s_ic[w][lane][k], s_src[w][k], sc);   // h ascending
            }
            // first-index argmax (strict >), identical in all lanes
            float bv = -INFINITY; int idx = 0;
            #pragma unroll
            for (int j = 0; j < 10; j++) {
                float v = __shfl_sync(FULL_MASK, sc, j);
                if (v > bv) { bv = v; idx = j; }
            }

            float item = s_ic[w][idx][h];          // broadcast gather (full fp32)
            sum_h += item;                         // sequential append-order sum
            if (g == 0) {
                g_out[(size_t)b * 96 + (size_t)t * 16 + h] = item;
                s_src[w][h] = __fdiv_rn(sum_h, (float)(t + 1));  // IEEE divide (next step's mean)
            }
        }
    }
}

extern "C" void kernel_launch(void* const* d_in, const int* in_sizes, int n_in,
                              void* d_out, int out_size) {
    const float* ui     = (const float*)d_in[0];
    const float* corpus = (const float*)d_in[1];
    const float* wp     = (const float*)d_in[2];
    const float* bp     = (const float*)d_in[3];
    const float* wk     = (const float*)d_in[4];
    const float* bk     = (const float*)d_in[5];
    float* out = (float*)d_out;
    int n_batch = in_sizes[0] / 16;
    // 6 blocks x 148 SMs resident (25.4 KB smem/block, ~45 regs) -> single wave, grid-stride.
    attn_greedy_kernel<<<888, 128>>>(ui, corpus, wp, bp, wk, bk, out, n_batch);
}

// round 5
// speedup vs baseline: 1.1497x; 1.1497x over previous
#include <cuda_runtime.h>
#include <math.h>
#include <cstdint>

#define FULL_MASK 0xFFFFFFFFu
typedef unsigned long long ull;

__device__ __forceinline__ ull pk2(float lo, float hi) {
    ull r; asm("mov.b64 %0, {%1, %2};" : "=l"(r) : "f"(lo), "f"(hi)); return r;
}
__device__ __forceinline__ void fma2(ull& d, ull a, ull b) {
    asm("fma.rn.f32x2 %0, %1, %2, %0;" : "+l"(d) : "l"(a), "l"(b));
}
__device__ __forceinline__ void unpk(ull v, float& a, float& b) {
    asm("mov.b64 {%0, %1}, %2;" : "=f"(a), "=f"(b) : "l"(v));
}

// bs=65536, S=10, D=100, H=16, 5 greedy steps. One warp per batch.
// lane = (h = lane&15, g = lane>>4); lane owns ic[5g+j][h], j=0..4.
//
// FROZEN numerics contract (bit-matches the reference; rel_err 9.3e-8 in R4):
//   - every dot: single-accumulator sequential-k fmaf chain (ascending k), bias AFTER
//   - f32x2 pairs two INDEPENDENT output chains (lo/hi rounded separately => bit-identical)
//   - src = mean(ui) via IEEE __fdiv_rn of the sequential append-order sum
//   - softmax skipped (monotone); first-index argmax via strict >
__global__ __launch_bounds__(128, 5)
void attn_greedy_kernel(const float* __restrict__ g_ui,     // [bs,16]
                        const float* __restrict__ g_corp,   // [bs,10,100]
                        const float* __restrict__ g_wp,     // [100,16]
                        const float* __restrict__ g_bp,     // [16]
                        const float* __restrict__ g_wk,     // [16,16]
                        const float* __restrict__ g_bk,     // [16]
                        float* __restrict__ g_out,          // [bs,6,16]
                        int n_batch)
{
    __shared__ __align__(16) float s_corp[4][1000];   // per-warp corpus tile (row stride 100)
    __shared__ __align__(16) float s_wpT[16][100];    // W_proj^T: [h][d] (float4-loadable rows)
    __shared__ __align__(16) float s_ic [4][10][28];  // ic row-major  (score + gather); stride 28
    __shared__ __align__(16) float s_icT[4][16][20];  // ic transposed [h][col], col = 8g+j; stride 20
    __shared__ __align__(16) float s_src[4][16];      // current mean(ui)

    const int tid  = threadIdx.x;
    const int w    = tid >> 5;
    const int lane = tid & 31;
    const int h    = lane & 15;
    const int g    = lane >> 4;

    for (int i = tid; i < 1600; i += 128) {           // stage W_proj^T once per block
        int d = i >> 4, hh = i & 15;
        s_wpT[hh][d] = g_wp[d * 16 + hh];
    }
    ull wk2[16];                                      // {Wk[k][h], Wk[k][h]} pairs
    #pragma unroll
    for (int k = 0; k < 16; k++) { float v = g_wk[k * 16 + h]; wk2[k] = pk2(v, v); }
    const float bp_h = g_bp[h];
    const float bk_h = g_bk[h];
    __syncthreads();

    const int wg = (blockIdx.x << 2) + w;
    const int nw = gridDim.x << 2;

    // ---- prefetch first batch's corpus into registers ----
    float4 cv[8];
    float  u_next = 0.f;
    if (wg < n_batch) {
        const float4* s4 = (const float4*)(g_corp + (size_t)wg * 1000);
        #pragma unroll
        for (int i = 0; i < 8; i++) { int idx = lane + 32 * i; if (idx < 250) cv[i] = s4[idx]; }
        u_next = g_ui[(size_t)wg * 16 + h];
    }

    for (int b = wg; b < n_batch; b += nw) {
        // ---- commit staged corpus to smem ----
        float4* dst4 = (float4*)s_corp[w];
        #pragma unroll
        for (int i = 0; i < 8; i++) { int idx = lane + 32 * i; if (idx < 250) dst4[idx] = cv[i]; }
        float u_h   = u_next;
        float sum_h = u_h;                            // append-order running sum
        if (g == 0) { g_out[(size_t)b * 96 + h] = u_h; s_src[w][h] = u_h; }
        __syncwarp();

        // ---- prefetch NEXT batch (DRAM latency hidden under projection) ----
        int bn = b + nw;
        if (bn < n_batch) {
            const float4* s4 = (const float4*)(g_corp + (size_t)bn * 1000);
            #pragma unroll
            for (int i = 0; i < 8; i++) { int idx = lane + 32 * i; if (idx < 250) cv[i] = s4[idx]; }
            u_next = g_ui[(size_t)bn * 16 + h];
        }

        // ---- projection: ic0[s][h] = seq-fma_{d=0..99} corp[s,d]*Wp[d,h], then +bp ----
        float acc[5] = {0.f, 0.f, 0.f, 0.f, 0.f};
        const float* crow = &s_corp[w][5 * g * 100];
        #pragma unroll
        for (int c = 0; c < 25; c++) {
            float4 wv = *(const float4*)&s_wpT[h][4 * c];
            #pragma unroll
            for (int j = 0; j < 5; j++) {
                float4 x = *(const float4*)(crow + j * 100 + 4 * c);
                acc[j] = fmaf(x.x, wv.x, acc[j]);     // d ascending
                acc[j] = fmaf(x.y, wv.y, acc[j]);
                acc[j] = fmaf(x.z, wv.z, acc[j]);
                acc[j] = fmaf(x.w, wv.w, acc[j]);
            }
        }
        #pragma unroll
        for (int j = 0; j < 5; j++) {
            float v = acc[j] + bp_h;
            s_ic [w][5*g + j][h]   = v;
            s_icT[w][h][8*g + j]   = v;
        }
        __syncwarp();

        // ---- 5 greedy steps ----
        #pragma unroll
        for (int t = 1; t <= 5; t++) {
            // W_k matmul from transposed layout: per k, LDS.128 (j0..3) + LDS.64 (j4,pad)
            ull a01 = 0ull, a23 = 0ull, a4 = 0ull;
            #pragma unroll
            for (int k = 0; k < 16; k++) {
                const float* p = &s_icT[w][k][8 * g];
                ulonglong2 v = *(const ulonglong2*)p;     // {ic[j0][k],ic[j1][k]} | {ic[j2][k],ic[j3][k]}
                ull v4 = *(const ull*)(p + 4);            // {ic[j4][k], pad}
                fma2(a01, v.x, wk2[k]);                   // two independent sequential-k chains
                fma2(a23, v.y, wk2[k]);
                fma2(a4 , v4 , wk2[k]);                   // hi half discarded
            }
            float nic[5], hi_dummy;
            unpk(a01, nic[0], nic[1]);
            unpk(a23, nic[2], nic[3]);
            unpk(a4 , nic[4], hi_dummy);
            #pragma unroll
            for (int j = 0; j < 5; j++) nic[j] += bk_h;   // bias after full reduction
            __syncwarp();                                 // all reads of old ic done (matmul + prev score/gather)
            #pragma unroll
            for (int j = 0; j < 5; j++) {
                s_ic [w][5*g + j][h] = nic[j];
                s_icT[w][h][8*g + j] = nic[j];
            }
            __syncwarp();                                 // new ic visible

            // score[s] = seq-fma_{h=0..15} ic[s,h]*src[h]  (lanes 0..9, vectorized loads)
            float sc = -INFINITY;
            if (lane < 10) {
                const float4* r  = (const float4*)s_ic[w][lane];
                const float4* sp = (const float4*)s_src[w];
                float a = 0.f;
                #pragma unroll
                for (int i = 0; i < 4; i++) {
                    float4 x = r[i], y = sp[i];
                    a = fmaf(x.x, y.x, a); a = fmaf(x.y, y.y, a);   // h ascending
                    a = fmaf(x.z, y.z, a); a = fmaf(x.w, y.w, a);
                }
                sc = a;
            }
            // first-index argmax (strict >), identical in all lanes
            float bv = -INFINITY; int idx = 0;
            #pragma unroll
            for (int j = 0; j < 10; j++) {
                float v = __shfl_sync(FULL_MASK, sc, j);  // warp-collective: also orders score reads
                if (v > bv) { bv = v; idx = j; }
            }

            float item = s_ic[w][idx][h];                 // broadcast gather
            sum_h += item;
            if (g == 0) {
                g_out[(size_t)b * 96 + (size_t)t * 16 + h] = item;
                if (t < 5) s_src[w][h] = __fdiv_rn(sum_h, (float)(t + 1));  // next step's mean
            }
        }
    }
}

extern "C" void kernel_launch(void* const* d_in, const int* in_sizes, int n_in,
                              void* d_out, int out_size) {
    const float* ui     = (const float*)d_in[0];
    const float* corpus = (const float*)d_in[1];
    const float* wp     = (const float*)d_in[2];
    const float* bp     = (const float*)d_in[3];
    const float* wk     = (const float*)d_in[4];
    const float* bk     = (const float*)d_in[5];
    float* out = (float*)d_out;
    int n_batch = in_sizes[0] / 16;
    // 5 blocks x 148 SMs (32.3 KB smem/block, ~95 regs within the 102 cap) -> single wave.
    attn_greedy_kernel<<<740, 128>>>(ui, corpus, wp, bp, wk, bk, out, n_batch);
}